// round 16
// baseline (speedup 1.0000x reference)
#include <cuda_runtime.h>
#include <cuda_bf16.h>
#include <cstdint>

// Problem constants (from reference)
#define S_GRID 7
#define B_BOX 2
#define C_CLS 20
#define CH (B_BOX * 5 + C_CLS)            // 30 channels
#define CELLS (S_GRID * S_GRID)           // 49
#define IMG_FLOATS (CELLS * CH)           // 1470
#define N_IMG 16384
#define T_TGT 32
#define LAMBDA_COORD 5.0f
#define LAMBDA_NOOBJ 0.5f

#define THREADS 256
#define WARPS_PER_BLK (THREADS / 32)      // 8 images per block
#define GRID_P (N_IMG / WARPS_PER_BLK)    // 2048 blocks

__device__ float g_partial[GRID_P];
__device__ unsigned int g_count;          // zero-init; returns to 0 every launch

__global__ void __launch_bounds__(THREADS)
yolo_quad_kernel(const float* __restrict__ outputs,
                 const float* __restrict__ tboxes,
                 const int*   __restrict__ tlabels,
                 float*       __restrict__ out)
{
    __shared__ float swsum[WARPS_PER_BLK];
    __shared__ int s_is_last;
    __shared__ double sd[THREADS];

    const int tid = threadIdx.x;
    const int wid = tid >> 5;
    const int lid = tid & 31;
    const int j     = lid & 3;            // lane within quad
    const int gbase = lid & ~3;           // quad leader lane id
    const int g     = lid >> 2;           // quad index (0..7)

    const int n = blockIdx.x * WARPS_PER_BLK + wid;   // image for this warp
    const float* __restrict__ img = outputs + (size_t)n * IMG_FLOATS;

    // ---- noobj: strided conf loads (R6 pattern, proven) ----
    const float2 nc0 = __ldg(reinterpret_cast<const float2*>(
        img + lid * CH + B_BOX * 4));
    float2 nc1 = make_float2(0.0f, 0.0f);
    if (lid < CELLS - 32)
        nc1 = __ldg(reinterpret_cast<const float2*>(
            img + (lid + 32) * CH + B_BOX * 4));
    const float v = nc0.x * nc0.x + nc0.y * nc0.y
                  + nc1.x * nc1.x + nc1.y * nc1.y;

    float lane_acc = (LAMBDA_NOOBJ / 98.0f) * v;

    const float cell = 1.0f / (float)S_GRID;

    // ---- 4 passes, 8 targets per pass, 4 lanes cooperate per target ----
    #pragma unroll
    for (int p = 0; p < 4; p++) {
        const int t = p * 8 + g;          // this quad's target

        // whole quad loads the same tb/label (broadcast within quad)
        const float4 tb = __ldg(reinterpret_cast<const float4*>(
            tboxes + ((size_t)n * T_TGT + t) * 4));
        const int label = __ldg(tlabels + (size_t)n * T_TGT + t);
        const int labp = 10 + label;      // window channel of the label logit

        const float tx = tb.x, ty = tb.y, tw = tb.z, th = tb.w;
        int gxi = (int)(tx / cell); gxi = min(max(gxi, 0), S_GRID - 1);
        int gyi = (int)(ty / cell); gyi = min(max(gyi, 0), S_GRID - 1);
        const float ox = (tx - (float)gxi * cell) / cell;
        const float oy = (ty - (float)gyi * cell) / cell;

        // 32-float aligned window containing the cell (R13 trick)
        const int cidx = gyi * S_GRID + gxi;
        const int abs_off = n * IMG_FLOATS + cidx * CH;   // even
        const int o2 = abs_off & 2;                        // 0 or 2
        const float4* __restrict__ w4 =
            reinterpret_cast<const float4*>(outputs + (abs_off - o2));

        // lane j holds window floats [4j..4j+3] and [16+4j..16+4j+3]
        const float4 q0 = __ldg(w4 + j);
        const float4 q1 = __ldg(w4 + 4 + j);

        // ---- softmax partials over this lane's 8 window slots ----
        // window slot i holds cell channel c = i - o2; logits are c in [10,30)
        float Zp = 0.0f, E2p = 0.0f, elp = 0.0f;
        const int cb0 = 4 * j - o2;        // channel of q0.x
        const int cb1 = 16 + 4 * j - o2;   // channel of q1.x
        {
            #define YSLOT(val, cc)                                   \
                do {                                                 \
                    const int _c = (cc);                             \
                    if (_c >= 10 && _c < 30) {                       \
                        const float _e = __expf(val);                \
                        Zp += _e; E2p += _e * _e;                    \
                        if (_c == labp) elp = _e;                    \
                    }                                                \
                } while (0)
            YSLOT(q0.x, cb0 + 0); YSLOT(q0.y, cb0 + 1);
            YSLOT(q0.z, cb0 + 2); YSLOT(q0.w, cb0 + 3);
            YSLOT(q1.x, cb1 + 0); YSLOT(q1.y, cb1 + 1);
            YSLOT(q1.z, cb1 + 2); YSLOT(q1.w, cb1 + 3);
            #undef YSLOT
        }
        // butterfly reduce within the quad (xor 1, xor 2)
        Zp  += __shfl_xor_sync(0xffffffffu, Zp, 1);
        E2p += __shfl_xor_sync(0xffffffffu, E2p, 1);
        elp += __shfl_xor_sync(0xffffffffu, elp, 1);
        Zp  += __shfl_xor_sync(0xffffffffu, Zp, 2);
        E2p += __shfl_xor_sync(0xffffffffu, E2p, 2);
        elp += __shfl_xor_sync(0xffffffffu, elp, 2);

        // ---- broadcast window[0..11] to all quad lanes (12 shuffles) ----
        const float w0  = __shfl_sync(0xffffffffu, q0.x, gbase + 0);
        const float w1  = __shfl_sync(0xffffffffu, q0.y, gbase + 0);
        const float w2  = __shfl_sync(0xffffffffu, q0.z, gbase + 0);
        const float w3  = __shfl_sync(0xffffffffu, q0.w, gbase + 0);
        const float w4f = __shfl_sync(0xffffffffu, q0.x, gbase + 1);
        const float w5  = __shfl_sync(0xffffffffu, q0.y, gbase + 1);
        const float w6  = __shfl_sync(0xffffffffu, q0.z, gbase + 1);
        const float w7  = __shfl_sync(0xffffffffu, q0.w, gbase + 1);
        const float w8  = __shfl_sync(0xffffffffu, q0.x, gbase + 2);
        const float w9  = __shfl_sync(0xffffffffu, q0.y, gbase + 2);
        const float w10 = __shfl_sync(0xffffffffu, q0.z, gbase + 2);
        const float w11 = __shfl_sync(0xffffffffu, q0.w, gbase + 2);

        // cell channels 0..9 (boxes + confs): cd[i] = window[i + o2]
        const bool odd = (o2 != 0);
        const float cd0 = odd ? w2  : w0;
        const float cd1 = odd ? w3  : w1;
        const float cd2 = odd ? w4f : w2;
        const float cd3 = odd ? w5  : w3;
        const float cd4 = odd ? w6  : w4f;
        const float cd5 = odd ? w7  : w5;
        const float cd6 = odd ? w8  : w6;
        const float cd7 = odd ? w9  : w7;
        const float cd8 = odd ? w10 : w8;
        const float cd9 = odd ? w11 : w9;

        // ---- IoU / argmax (division-free, identical math to R13) ----
        const float x11 = tx - tw * 0.5f, x12 = tx + tw * 0.5f;
        const float y11 = ty - th * 0.5f, y12 = ty + th * 0.5f;
        const float t_area = tw * th;

        float in0, u0, in1, u1, px0, py0, px1, py1;
        {
            const float gx = (cd0 + (float)gxi) * cell;
            const float gy = (cd1 + (float)gyi) * cell;
            px0 = gx; py0 = gy;
            float iw = fminf(x12, gx + cd2 * 0.5f) - fmaxf(x11, gx - cd2 * 0.5f);
            float ih = fminf(y12, gy + cd3 * 0.5f) - fmaxf(y11, gy - cd3 * 0.5f);
            iw = fmaxf(iw, 0.0f); ih = fmaxf(ih, 0.0f);
            in0 = iw * ih;
            u0  = fmaxf(t_area + cd2 * cd3 - in0, 1e-6f);
        }
        {
            const float gx = (cd4 + (float)gxi) * cell;
            const float gy = (cd5 + (float)gyi) * cell;
            px1 = gx; py1 = gy;
            float iw = fminf(x12, gx + cd6 * 0.5f) - fmaxf(x11, gx - cd6 * 0.5f);
            float ih = fminf(y12, gy + cd7 * 0.5f) - fmaxf(y11, gy - cd7 * 0.5f);
            iw = fmaxf(iw, 0.0f); ih = fmaxf(ih, 0.0f);
            in1 = iw * ih;
            u1  = fmaxf(t_area + cd6 * cd7 - in1, 1e-6f);
        }
        // jnp.argmax tie-break: pick box 1 only if strictly greater
        const int best = (in1 * u0 > in0 * u1) ? 1 : 0;

        const float bx = best ? px1 : px0;
        const float by = best ? py1 : py0;
        const float bw = fmaxf(best ? cd6 : cd2, 1e-6f);
        const float bh = fmaxf(best ? cd7 : cd3, 1e-6f);
        const float twc = fmaxf(tw, 1e-6f);
        const float thc = fmaxf(th, 1e-6f);

        const float dx = bx - ox;
        const float dy = by - oy;
        const float dw = sqrtf(bw) - sqrtf(twc);
        const float dh = sqrtf(bh) - sqrtf(thc);
        const float box_loss = dx * dx + dy * dy + dw * dw + dh * dh;

        const float bc = best ? cd9 : cd8;
        const float obj_loss = (bc - 1.0f) * (bc - 1.0f);

        // class term: mean_c (p_c - onehot)^2 = (E2/Z^2 - 2 e_lab/Z + 1)/20
        const float invZ = __fdividef(1.0f, Zp);
        const float class_loss =
            (E2p * invZ * invZ - 2.0f * elp * invZ + 1.0f)
            * (1.0f / (float)C_CLS);

        // all 4 quad lanes hold the identical target loss; add 1/4 each
        lane_acc += 0.25f * (LAMBDA_COORD * box_loss + class_loss + obj_loss);
    }

    // ---- warp reduction, then block partial ----
    #pragma unroll
    for (int o = 16; o; o >>= 1)
        lane_acc += __shfl_down_sync(0xffffffffu, lane_acc, o);
    if (lid == 0) swsum[wid] = lane_acc;
    __syncthreads();

    if (tid == 0) {
        float bsum = 0.0f;
        #pragma unroll
        for (int w = 0; w < WARPS_PER_BLK; w++) bsum += swsum[w];
        g_partial[blockIdx.x] = bsum;
        __threadfence();
        const unsigned old = atomicAdd(&g_count, 1u);
        s_is_last = (old == (unsigned)(gridDim.x - 1));
    }
    __syncthreads();

    // ---- last block: deterministic final reduction over 2048 partials ----
    if (s_is_last) {
        double acc = 0.0;
        for (int i = tid; i < GRID_P; i += THREADS)
            acc += (double)g_partial[i];
        sd[tid] = acc;
        __syncthreads();
        #pragma unroll
        for (int off = THREADS / 2; off; off >>= 1) {
            if (tid < off) sd[tid] += sd[tid + off];
            __syncthreads();
        }
        if (tid == 0) {
            out[0] = (float)(sd[0] / (double)N_IMG);
            g_count = 0;   // reset for next graph replay
        }
    }
}

extern "C" void kernel_launch(void* const* d_in, const int* in_sizes, int n_in,
                              void* d_out, int out_size)
{
    const float* outputs = (const float*)d_in[0];
    const float* tboxes  = (const float*)d_in[1];
    const int*   tlabels = (const int*)d_in[2];
    float* out = (float*)d_out;

    yolo_quad_kernel<<<GRID_P, THREADS>>>(outputs, tboxes, tlabels, out);
}

// round 17
// speedup vs baseline: 1.5131x; 1.5131x over previous
#include <cuda_runtime.h>
#include <cuda_bf16.h>
#include <cstdint>

// Problem constants (from reference)
#define S_GRID 7
#define B_BOX 2
#define C_CLS 20
#define CH (B_BOX * 5 + C_CLS)            // 30 channels
#define CELLS (S_GRID * S_GRID)           // 49
#define IMG_FLOATS (CELLS * CH)           // 1470
#define N_IMG 16384
#define T_TGT 32
#define LAMBDA_COORD 5.0f
#define LAMBDA_NOOBJ 0.5f

#define THREADS 256
#define WARPS_PER_BLK (THREADS / 32)      // 8
#define BLOCKS 1024                        // 8192 warps x 2 images = 16384
#define IMG_STRIDE (BLOCKS * WARPS_PER_BLK)   // 8192

__device__ float g_partial[BLOCKS];
__device__ unsigned int g_count;          // zero-init; returns to 0 every launch

// per-target math given cell data (5 float2 regs) + streamed logits
__device__ __forceinline__ float target_math(
    const float* __restrict__ cs,          // cell base (global)
    float2 b0a, float2 b0b, float2 b1a, float2 b1b, float2 cf,
    float tx, float ty, float tw, float th,
    int gxi, int gyi, float ox, float oy, int label)
{
    const float cell = 1.0f / (float)S_GRID;
    const float x11 = tx - tw * 0.5f, x12 = tx + tw * 0.5f;
    const float y11 = ty - th * 0.5f, y12 = ty + th * 0.5f;
    const float t_area = tw * th;

    float in0, u0, in1, u1, px0, py0, px1, py1;
    {
        const float gx = (b0a.x + (float)gxi) * cell;
        const float gy = (b0a.y + (float)gyi) * cell;
        px0 = gx; py0 = gy;
        float iw = fminf(x12, gx + b0b.x * 0.5f) - fmaxf(x11, gx - b0b.x * 0.5f);
        float ih = fminf(y12, gy + b0b.y * 0.5f) - fmaxf(y11, gy - b0b.y * 0.5f);
        iw = fmaxf(iw, 0.0f); ih = fmaxf(ih, 0.0f);
        in0 = iw * ih;
        u0  = fmaxf(t_area + b0b.x * b0b.y - in0, 1e-6f);
    }
    {
        const float gx = (b1a.x + (float)gxi) * cell;
        const float gy = (b1a.y + (float)gyi) * cell;
        px1 = gx; py1 = gy;
        float iw = fminf(x12, gx + b1b.x * 0.5f) - fmaxf(x11, gx - b1b.x * 0.5f);
        float ih = fminf(y12, gy + b1b.y * 0.5f) - fmaxf(y11, gy - b1b.y * 0.5f);
        iw = fmaxf(iw, 0.0f); ih = fmaxf(ih, 0.0f);
        in1 = iw * ih;
        u1  = fmaxf(t_area + b1b.x * b1b.y - in1, 1e-6f);
    }
    // jnp.argmax tie-break: pick box 1 only if strictly greater (unions > 0)
    const int best = (in1 * u0 > in0 * u1) ? 1 : 0;

    const float bx = best ? px1 : px0;
    const float by = best ? py1 : py0;
    const float bw = fmaxf(best ? b1b.x : b0b.x, 1e-6f);
    const float bh = fmaxf(best ? b1b.y : b0b.y, 1e-6f);
    const float twc = fmaxf(tw, 1e-6f);
    const float thc = fmaxf(th, 1e-6f);

    const float dx = bx - ox;
    const float dy = by - oy;
    const float dw = sqrtf(bw) - sqrtf(twc);
    const float dh = sqrtf(bh) - sqrtf(thc);
    const float box_loss = dx * dx + dy * dy + dw * dw + dh * dh;

    const float bc = best ? cf.y : cf.x;
    const float obj_loss = (bc - 1.0f) * (bc - 1.0f);

    // class term: softmax without max-subtraction (logits ~ N(0,1));
    // mean_c (p_c - onehot)^2 = (E2/Z^2 - 2 e_lab/Z + 1)/20
    const float2* __restrict__ c2 = reinterpret_cast<const float2*>(cs);
    float Z = 0.0f, E2 = 0.0f, e_lab = 0.0f;
    #pragma unroll
    for (int i = 0; i < C_CLS / 2; i++) {
        const float2 p = __ldg(c2 + 5 + i);
        const float e0 = __expf(p.x);
        const float e1 = __expf(p.y);
        Z  += e0 + e1;
        E2 += e0 * e0 + e1 * e1;
        if (label == 2 * i)     e_lab = e0;
        if (label == 2 * i + 1) e_lab = e1;
    }
    const float invZ = __fdividef(1.0f, Z);
    const float class_loss =
        (E2 * invZ * invZ - 2.0f * e_lab * invZ + 1.0f) * (1.0f / (float)C_CLS);

    return LAMBDA_COORD * box_loss + class_loss + obj_loss;
}

__global__ void __launch_bounds__(THREADS)
yolo_pipe_kernel(const float* __restrict__ outputs,
                 const float* __restrict__ tboxes,
                 const int*   __restrict__ tlabels,
                 float*       __restrict__ out)
{
    __shared__ float swsum[WARPS_PER_BLK];
    __shared__ int s_is_last;
    __shared__ double sd[THREADS];

    const int tid = threadIdx.x;
    const int wid = tid >> 5;
    const int lid = tid & 31;

    const int na = blockIdx.x * WARPS_PER_BLK + wid;
    const int nb = na + IMG_STRIDE;
    const float* __restrict__ imga = outputs + (size_t)na * IMG_FLOATS;
    const float* __restrict__ imgb = outputs + (size_t)nb * IMG_FLOATS;

    // ========== stage 1: 8 independent loads for BOTH images ==========
    const float4 tba = *reinterpret_cast<const float4*>(
        tboxes + ((size_t)na * T_TGT + lid) * 4);
    const float4 tbb = *reinterpret_cast<const float4*>(
        tboxes + ((size_t)nb * T_TGT + lid) * 4);
    const int laba = __ldg(tlabels + (size_t)na * T_TGT + lid);
    const int labb = __ldg(tlabels + (size_t)nb * T_TGT + lid);

    const float2 nca0 = __ldg(reinterpret_cast<const float2*>(
        imga + lid * CH + B_BOX * 4));
    const float2 ncb0 = __ldg(reinterpret_cast<const float2*>(
        imgb + lid * CH + B_BOX * 4));
    float2 nca1 = make_float2(0.0f, 0.0f);
    float2 ncb1 = make_float2(0.0f, 0.0f);
    if (lid < CELLS - 32) {
        nca1 = __ldg(reinterpret_cast<const float2*>(
            imga + (lid + 32) * CH + B_BOX * 4));
        ncb1 = __ldg(reinterpret_cast<const float2*>(
            imgb + (lid + 32) * CH + B_BOX * 4));
    }

    const float cell = 1.0f / (float)S_GRID;

    // ========== stage 2a: resolve image A's cell, issue its loads ==========
    const float txa = tba.x, tya = tba.y, twa = tba.z, tha = tba.w;
    int gxa = (int)(txa / cell); gxa = min(max(gxa, 0), S_GRID - 1);
    int gya = (int)(tya / cell); gya = min(max(gya, 0), S_GRID - 1);
    const float oxa = (txa - (float)gxa * cell) / cell;
    const float oya = (tya - (float)gya * cell) / cell;
    const float* __restrict__ csa = imga + (gya * S_GRID + gxa) * CH;
    const float2* __restrict__ ca2 = reinterpret_cast<const float2*>(csa);
    const float2 a0a = __ldg(ca2 + 0);
    const float2 a0b = __ldg(ca2 + 1);
    const float2 a1a = __ldg(ca2 + 2);
    const float2 a1b = __ldg(ca2 + 3);
    const float2 acf = __ldg(ca2 + 4);

    // ========== stage 2b: resolve image B's cell, issue its loads ==========
    const float txb = tbb.x, tyb = tbb.y, twb = tbb.z, thb = tbb.w;
    int gxb = (int)(txb / cell); gxb = min(max(gxb, 0), S_GRID - 1);
    int gyb = (int)(tyb / cell); gyb = min(max(gyb, 0), S_GRID - 1);
    const float oxb = (txb - (float)gxb * cell) / cell;
    const float oyb = (tyb - (float)gyb * cell) / cell;
    const float* __restrict__ csb = imgb + (gyb * S_GRID + gxb) * CH;
    const float2* __restrict__ cb2 = reinterpret_cast<const float2*>(csb);
    const float2 b0a = __ldg(cb2 + 0);
    const float2 b0b = __ldg(cb2 + 1);
    const float2 b1a = __ldg(cb2 + 2);
    const float2 b1b = __ldg(cb2 + 3);
    const float2 bcf = __ldg(cb2 + 4);

    // ========== stage 3: noobj math (loads all in flight) ==========
    const float va = nca0.x * nca0.x + nca0.y * nca0.y
                   + nca1.x * nca1.x + nca1.y * nca1.y;
    const float vb = ncb0.x * ncb0.x + ncb0.y * ncb0.y
                   + ncb1.x * ncb1.x + ncb1.y * ncb1.y;

    float lane_acc = (LAMBDA_NOOBJ / 98.0f) * (va + vb);

    // ========== stage 4: per-target math, image A then image B ==========
    lane_acc += target_math(csa, a0a, a0b, a1a, a1b, acf,
                            txa, tya, twa, tha, gxa, gya, oxa, oya, laba);
    lane_acc += target_math(csb, b0a, b0b, b1a, b1b, bcf,
                            txb, tyb, twb, thb, gxb, gyb, oxb, oyb, labb);

    // ---- warp reduction, then block partial ----
    #pragma unroll
    for (int o = 16; o; o >>= 1)
        lane_acc += __shfl_down_sync(0xffffffffu, lane_acc, o);
    if (lid == 0) swsum[wid] = lane_acc;
    __syncthreads();

    if (tid == 0) {
        float bsum = 0.0f;
        #pragma unroll
        for (int w = 0; w < WARPS_PER_BLK; w++) bsum += swsum[w];
        g_partial[blockIdx.x] = bsum;
        __threadfence();
        const unsigned old = atomicAdd(&g_count, 1u);
        s_is_last = (old == (unsigned)(gridDim.x - 1));
    }
    __syncthreads();

    // ---- last block: deterministic final reduction over 1024 partials ----
    if (s_is_last) {
        double acc = 0.0;
        for (int i = tid; i < BLOCKS; i += THREADS)
            acc += (double)g_partial[i];
        sd[tid] = acc;
        __syncthreads();
        #pragma unroll
        for (int off = THREADS / 2; off; off >>= 1) {
            if (tid < off) sd[tid] += sd[tid + off];
            __syncthreads();
        }
        if (tid == 0) {
            out[0] = (float)(sd[0] / (double)N_IMG);
            g_count = 0;   // reset for next graph replay
        }
    }
}

extern "C" void kernel_launch(void* const* d_in, const int* in_sizes, int n_in,
                              void* d_out, int out_size)
{
    const float* outputs = (const float*)d_in[0];
    const float* tboxes  = (const float*)d_in[1];
    const int*   tlabels = (const int*)d_in[2];
    float* out = (float*)d_out;

    yolo_pipe_kernel<<<BLOCKS, THREADS>>>(outputs, tboxes, tlabels, out);
}